// round 7
// baseline (speedup 1.0000x reference)
#include <cuda_runtime.h>
#include <cuda_fp16.h>
#include <cuda_bf16.h>
#include <math.h>

// Problem constants (fixed by the dataset)
#define NN 100000
#define NF 256
#define NH 16
#define NC 16
#define NE 3200000

#define SCAN_CHUNK 4096
#define SCAN_BLOCKS 25   // ceil(100000/4096)

typedef unsigned long long u64;

// ---------------- device scratch (static, allowed) ----------------
__device__ int   g_cnt[NN];            // in-degree (no self loop)
__device__ int   g_rowstart[NN + 1];   // CSR row offsets (block-LOCAL scan)
__device__ int   g_rowfinal[NN + 1];   // CSR row offsets (final)
__device__ int   g_blocksums[SCAN_BLOCKS];
__device__ float g_dinv[NN];           // rsqrt(indeg+1)
__device__ float g_h[NN * NH];         // x@W1 (fp32, unscaled)
__device__ uint4 g_hh[NN * 2];         // fp16 (x@W1)*dinv : 16 halves/node = 2 uint4
__device__ uint4 g_h1h[NN * 2];        // fp16 GCN output
__device__ int   g_srcsorted[NE];      // src ids grouped by dst
__device__ int   g_rank[NE];           // per-edge rank within its dst bucket

// ---------------- f32x2 helpers (FFMA2 is PTX-only) ----------------
__device__ __forceinline__ u64 pk2(float a, float b) {
    u64 r; asm("mov.b64 %0, {%1, %2};" : "=l"(r) : "f"(a), "f"(b)); return r;
}
__device__ __forceinline__ u64 dup2(float a) {
    u64 r; asm("mov.b64 %0, {%1, %1};" : "=l"(r) : "f"(a)); return r;
}
__device__ __forceinline__ u64 ffma2(u64 a, u64 b, u64 c) {
    u64 d; asm("fma.rn.f32x2 %0, %1, %2, %3;" : "=l"(d) : "l"(a), "l"(b), "l"(c)); return d;
}
__device__ __forceinline__ float2 unpk2(u64 a) {
    float2 f; asm("mov.b64 {%0, %1}, %2;" : "=f"(f.x), "=f"(f.y) : "l"(a)); return f;
}

// unpack a uint4 of 8 halves into 4 float2, accumulate
__device__ __forceinline__ void acc_h8(const uint4& v, float2& a0, float2& a1,
                                       float2& a2, float2& a3) {
    __half2 h0 = *reinterpret_cast<const __half2*>(&v.x);
    __half2 h1 = *reinterpret_cast<const __half2*>(&v.y);
    __half2 h2 = *reinterpret_cast<const __half2*>(&v.z);
    __half2 h3 = *reinterpret_cast<const __half2*>(&v.w);
    float2 f0 = __half22float2(h0), f1 = __half22float2(h1);
    float2 f2 = __half22float2(h2), f3 = __half22float2(h3);
    a0.x += f0.x; a0.y += f0.y; a1.x += f1.x; a1.y += f1.y;
    a2.x += f2.x; a2.y += f2.y; a3.x += f3.x; a3.y += f3.y;
}

__device__ __forceinline__ uint4 pack_h8(float2 a0, float2 a1, float2 a2, float2 a3) {
    __half2 h0 = __floats2half2_rn(a0.x, a0.y);
    __half2 h1 = __floats2half2_rn(a1.x, a1.y);
    __half2 h2 = __floats2half2_rn(a2.x, a2.y);
    __half2 h3 = __floats2half2_rn(a3.x, a3.y);
    uint4 o;
    o.x = *reinterpret_cast<unsigned*>(&h0);
    o.y = *reinterpret_cast<unsigned*>(&h1);
    o.z = *reinterpret_cast<unsigned*>(&h2);
    o.w = *reinterpret_cast<unsigned*>(&h3);
    return o;
}

#define RED8(mask, D)                                        \
    a0.x += __shfl_xor_sync(mask, a0.x, D);                  \
    a0.y += __shfl_xor_sync(mask, a0.y, D);                  \
    a1.x += __shfl_xor_sync(mask, a1.x, D);                  \
    a1.y += __shfl_xor_sync(mask, a1.y, D);                  \
    a2.x += __shfl_xor_sync(mask, a2.x, D);                  \
    a2.y += __shfl_xor_sync(mask, a2.y, D);                  \
    a3.x += __shfl_xor_sync(mask, a3.x, D);                  \
    a3.y += __shfl_xor_sync(mask, a3.y, D);

// ---------------- kernels ----------------

// histogram of dst + record each edge's rank within its bucket
__global__ void k_count(const int* __restrict__ dst) {
    int i = blockIdx.x * blockDim.x + threadIdx.x;   // i < NE/4
    int4 d = ((const int4*)dst)[i];
    int4 r;
    r.x = atomicAdd(&g_cnt[d.x], 1);
    r.y = atomicAdd(&g_cnt[d.y], 1);
    r.z = atomicAdd(&g_cnt[d.z], 1);
    r.w = atomicAdd(&g_cnt[d.w], 1);
    ((int4*)g_rank)[i] = r;
}

// per-block exclusive scan of g_cnt chunk -> g_rowstart (block-local), totals -> g_blocksums
__global__ void k_scan_local() {
    __shared__ int s[SCAN_CHUNK];
    __shared__ int tsum[256];
    int t = threadIdx.x;
    int base = blockIdx.x * SCAN_CHUNK;
    for (int i = t; i < SCAN_CHUNK; i += 256) {
        int idx = base + i;
        s[i] = (idx < NN) ? g_cnt[idx] : 0;
    }
    __syncthreads();

    int loc[16];
    int run = 0;
#pragma unroll
    for (int i = 0; i < 16; i++) {
        run += s[t * 16 + i];
        loc[i] = run;                 // inclusive within thread
    }
    tsum[t] = run;
    __syncthreads();
    for (int off = 1; off < 256; off <<= 1) {
        int v = (t >= off) ? tsum[t - off] : 0;
        __syncthreads();
        tsum[t] += v;
        __syncthreads();
    }
    int ex = (t == 0) ? 0 : tsum[t - 1];
#pragma unroll
    for (int i = 0; i < 16; i++) {
        s[t * 16 + i] = ex + (i ? loc[i - 1] : 0);   // exclusive per element
    }
    __syncthreads();
    for (int i = t; i < SCAN_CHUNK; i += 256) {
        int idx = base + i;
        if (idx < NN) g_rowstart[idx] = s[i];
    }
    if (t == 0) g_blocksums[blockIdx.x] = tsum[255];
}

// finalize rowstart into g_rowfinal + dinv (runs on SIDE stream, overlaps scatter)
__global__ void k_fixup() {
    __shared__ int sbs[SCAN_BLOCKS];
    int t = threadIdx.x;
    if (t < SCAN_BLOCKS) sbs[t] = g_blocksums[t];
    __syncthreads();
    int i = blockIdx.x * 256 + t;
    if (i >= NN) return;
    int chunk = i >> 12;          // / SCAN_CHUNK
    int off = 0;
    for (int b = 0; b < chunk; b++) off += sbs[b];
    g_rowfinal[i] = g_rowstart[i] + off;
    g_dinv[i] = rsqrtf((float)(g_cnt[i] + 1));
    if (i == 0) g_rowfinal[NN] = NE;
}

// atomic-free CSR scatter using LOCAL rowstart + smem block sums (no fixup dep)
__global__ void __launch_bounds__(256)
k_scatter(const int* __restrict__ src, const int* __restrict__ dst) {
    __shared__ int sbs[SCAN_BLOCKS + 1];
    int t = threadIdx.x;
    if (t <= SCAN_BLOCKS) {
        int acc = 0;
        for (int b = 0; b < t; b++) acc += g_blocksums[b];   // tiny (25)
        sbs[t] = acc;
    }
    __syncthreads();
    int i = blockIdx.x * 256 + t;   // i < NE/4
    int4 s = ((const int4*)src)[i];
    int4 d = ((const int4*)dst)[i];
    int4 r = ((const int4*)g_rank)[i];
    int p0 = __ldg(&g_rowstart[d.x]) + sbs[d.x >> 12] + r.x;
    int p1 = __ldg(&g_rowstart[d.y]) + sbs[d.y >> 12] + r.y;
    int p2 = __ldg(&g_rowstart[d.z]) + sbs[d.z >> 12] + r.z;
    int p3 = __ldg(&g_rowstart[d.w]) + sbs[d.w >> 12] + r.w;
    g_srcsorted[p0] = s.x;
    g_srcsorted[p1] = s.y;
    g_srcsorted[p2] = s.z;
    g_srcsorted[p3] = s.w;
}

// g_h[n,:] = x[n,:] @ W1   (UNscaled fp32 — no CSR dependency; 4 nodes/thread)
__global__ void __launch_bounds__(256)
k_gemm1(const float* __restrict__ x, const float* __restrict__ W1) {
    __shared__ float sW[NF * NH];   // 16 KB
    int t = threadIdx.x;
    for (int i = t; i < NF * NH; i += 256) sW[i] = W1[i];
    __syncthreads();

    int q = t & 3;
    int slot = t >> 2;                 // 0..63
    int base = blockIdx.x * 256;
    int n0 = base + slot;
    int n1 = n0 + 64, n2 = n0 + 128, n3 = n0 + 192;
    int c0 = min(n0, NN - 1), c1 = min(n1, NN - 1);
    int c2 = min(n2, NN - 1), c3 = min(n3, NN - 1);

    const float4* x0 = (const float4*)(x + (size_t)c0 * NF);
    const float4* x1 = (const float4*)(x + (size_t)c1 * NF);
    const float4* x2 = (const float4*)(x + (size_t)c2 * NF);
    const float4* x3 = (const float4*)(x + (size_t)c3 * NF);
    const float4* w4 = (const float4*)sW;

    u64 a00 = 0, a01 = 0, a10 = 0, a11 = 0, a20 = 0, a21 = 0, a30 = 0, a31 = 0;

#define NODE_STEP(V, A0, A1)                                        \
    do {                                                            \
        u64 dx = dup2((V).x), dy = dup2((V).y);                     \
        u64 dz = dup2((V).z), dw = dup2((V).w);                     \
        A0 = ffma2(dx, w0a, A0); A1 = ffma2(dx, w0b, A1);           \
        A0 = ffma2(dy, w1a, A0); A1 = ffma2(dy, w1b, A1);           \
        A0 = ffma2(dz, w2a, A0); A1 = ffma2(dz, w2b, A1);           \
        A0 = ffma2(dw, w3a, A0); A1 = ffma2(dw, w3b, A1);           \
    } while (0)

#pragma unroll 4
    for (int kk = 0; kk < 64; kk++) {
        float4 v0 = __ldcs(&x0[kk]);
        float4 v1 = __ldcs(&x1[kk]);
        float4 v2 = __ldcs(&x2[kk]);
        float4 v3 = __ldcs(&x3[kk]);
        int kb = kk * 16 + q;
        float4 w0 = w4[kb];
        float4 w1 = w4[kb + 4];
        float4 w2 = w4[kb + 8];
        float4 w3 = w4[kb + 12];
        u64 w0a = pk2(w0.x, w0.y), w0b = pk2(w0.z, w0.w);
        u64 w1a = pk2(w1.x, w1.y), w1b = pk2(w1.z, w1.w);
        u64 w2a = pk2(w2.x, w2.y), w2b = pk2(w2.z, w2.w);
        u64 w3a = pk2(w3.x, w3.y), w3b = pk2(w3.z, w3.w);
        NODE_STEP(v0, a00, a01);
        NODE_STEP(v1, a10, a11);
        NODE_STEP(v2, a20, a21);
        NODE_STEP(v3, a30, a31);
    }
#undef NODE_STEP

    {
        int ns[4] = {n0, n1, n2, n3};
        u64 lo[4] = {a00, a10, a20, a30};
        u64 hi[4] = {a01, a11, a21, a31};
#pragma unroll
        for (int j = 0; j < 4; j++) {
            int n = ns[j];
            if (n < NN) {
                float2 l = unpk2(lo[j]), h = unpk2(hi[j]);
                *(float4*)&g_h[n * NH + q * 4] = make_float4(l.x, l.y, h.x, h.y);
            }
        }
    }
}

// g_hh[n,:] = half(g_h[n,:] * dinv[n]) — thread handles half a row (8 feats)
__global__ void k_scale() {
    int i = blockIdx.x * blockDim.x + threadIdx.x;   // i < NN*2
    if (i >= NN * 2) return;
    int n = i >> 1, p = i & 1;
    float dv = g_dinv[n];
    const float4* r = (const float4*)&g_h[n * NH + p * 8];
    float4 a = r[0], b = r[1];
    g_hh[i] = pack_h8(make_float2(a.x * dv, a.y * dv), make_float2(a.z * dv, a.w * dv),
                      make_float2(b.x * dv, b.y * dv), make_float2(b.z * dv, b.w * dv));
}

// GCN aggregate (fp16 gather): h1 = half(dinv*(sum g_hh[src] + g_hh[n]) + b1)
// one warp per node; 16 edge-slots x 2 lanes (each lane = 8 feats = 16B)
__global__ void k_gcn(const float* __restrict__ b1) {
    int gw = (blockIdx.x * blockDim.x + threadIdx.x) >> 5;
    int lane = threadIdx.x & 31;
    if (gw >= NN) return;
    int n = gw;
    int start = __ldg(&g_rowfinal[n]);
    int end   = __ldg(&g_rowfinal[n + 1]);
    int grp = lane >> 1, q = lane & 1;

    float2 a0 = {0, 0}, a1 = {0, 0}, a2 = {0, 0}, a3 = {0, 0};
    for (int j = start + grp; j < end; j += 16) {
        int s = __ldg(&g_srcsorted[j]);
        uint4 v = __ldg(&g_hh[s * 2 + q]);
        acc_h8(v, a0, a1, a2, a3);
    }
    RED8(0xffffffffu, 2); RED8(0xffffffffu, 4);
    RED8(0xffffffffu, 8); RED8(0xffffffffu, 16);

    if (lane < 2) {
        uint4 sv = g_hh[n * 2 + lane];
        float2 s0 = {0, 0}, s1 = {0, 0}, s2 = {0, 0}, s3 = {0, 0};
        acc_h8(sv, s0, s1, s2, s3);
        float dv = g_dinv[n];
        const float4* b4 = (const float4*)b1;
        float4 bA = __ldg(&b4[lane * 2]), bB = __ldg(&b4[lane * 2 + 1]);
        float2 r0 = {(a0.x + s0.x) * dv + bA.x, (a0.y + s0.y) * dv + bA.y};
        float2 r1 = {(a1.x + s1.x) * dv + bA.z, (a1.y + s1.y) * dv + bA.w};
        float2 r2 = {(a2.x + s2.x) * dv + bB.x, (a2.y + s2.y) * dv + bB.y};
        float2 r3 = {(a3.x + s3.x) * dv + bB.z, (a3.y + s3.y) * dv + bB.w};
        g_h1h[n * 2 + lane] = pack_h8(r0, r1, r2, r3);
    }
}

// SAGE (fp16 gather): agg = mean h1[src]; out = agg@Wl + h1[n]@Wr + b2; log_softmax
__global__ void k_sage(const float* __restrict__ Wl, const float* __restrict__ Wr,
                       const float* __restrict__ b2, float* __restrict__ out) {
    __shared__ float sWl[NH * NC], sWr[NH * NC], sB2[NC];
    __shared__ float sAgg[8][16], sH1[8][16];
    int t = threadIdx.x;
    for (int i = t; i < NH * NC; i += 256) { sWl[i] = Wl[i]; sWr[i] = Wr[i]; }
    if (t < NC) sB2[t] = b2[t];
    __syncthreads();

    int wib = t >> 5, lane = t & 31;
    int n = blockIdx.x * 8 + wib;
    if (n >= NN) return;

    int start = __ldg(&g_rowfinal[n]);
    int end   = __ldg(&g_rowfinal[n + 1]);
    int grp = lane >> 1, q = lane & 1;

    float2 a0 = {0, 0}, a1 = {0, 0}, a2 = {0, 0}, a3 = {0, 0};
    for (int j = start + grp; j < end; j += 16) {
        int s = __ldg(&g_srcsorted[j]);
        uint4 v = __ldg(&g_h1h[s * 2 + q]);
        acc_h8(v, a0, a1, a2, a3);
    }
    RED8(0xffffffffu, 2); RED8(0xffffffffu, 4);
    RED8(0xffffffffu, 8); RED8(0xffffffffu, 16);

    if (lane < 2) {
        float inv = 1.0f / fmaxf((float)(end - start), 1.0f);
        float* ag = &sAgg[wib][lane * 8];
        ag[0] = a0.x * inv; ag[1] = a0.y * inv; ag[2] = a1.x * inv; ag[3] = a1.y * inv;
        ag[4] = a2.x * inv; ag[5] = a2.y * inv; ag[6] = a3.x * inv; ag[7] = a3.y * inv;
        uint4 hv = g_h1h[n * 2 + lane];
        float2 h0 = {0, 0}, h1 = {0, 0}, h2 = {0, 0}, h3 = {0, 0};
        acc_h8(hv, h0, h1, h2, h3);
        float* hh = &sH1[wib][lane * 8];
        hh[0] = h0.x; hh[1] = h0.y; hh[2] = h1.x; hh[3] = h1.y;
        hh[4] = h2.x; hh[5] = h2.y; hh[6] = h3.x; hh[7] = h3.y;
    }
    __syncwarp();
    if (lane < 16) {
        float o = sB2[lane];
#pragma unroll
        for (int k = 0; k < 16; k++) {
            o += sAgg[wib][k] * sWl[k * NC + lane] + sH1[wib][k] * sWr[k * NC + lane];
        }
        float m = o;
#pragma unroll
        for (int d = 8; d >= 1; d >>= 1)
            m = fmaxf(m, __shfl_xor_sync(0xffffu, m, d));
        float e = __expf(o - m);
        float ssum = e;
#pragma unroll
        for (int d = 8; d >= 1; d >>= 1)
            ssum += __shfl_xor_sync(0xffffu, ssum, d);
        out[n * NC + lane] = (o - m) - __logf(ssum);
    }
}

// ---------------- launch (fork-join two-stream graph) ----------------
static cudaStream_t s2 = nullptr;
static cudaEvent_t evFork = nullptr, evScan = nullptr, evSide = nullptr;

extern "C" void kernel_launch(void* const* d_in, const int* in_sizes, int n_in,
                              void* d_out, int out_size) {
    const float* x  = (const float*)d_in[0];
    const int*   ei = (const int*)d_in[1];
    const float* W1 = (const float*)d_in[2];
    const float* b1 = (const float*)d_in[3];
    const float* Wl = (const float*)d_in[4];
    const float* Wr = (const float*)d_in[5];
    const float* b2 = (const float*)d_in[6];
    float* out = (float*)d_out;

    const int* src = ei;
    const int* dst = ei + NE;

    if (!s2) {
        cudaStreamCreateWithFlags(&s2, cudaStreamNonBlocking);
        cudaEventCreateWithFlags(&evFork, cudaEventDisableTiming);
        cudaEventCreateWithFlags(&evScan, cudaEventDisableTiming);
        cudaEventCreateWithFlags(&evSide, cudaEventDisableTiming);
    }

    void* cnt_ptr = nullptr;
    cudaGetSymbolAddress(&cnt_ptr, g_cnt);

    // fork: side stream runs gemm (no CSR deps) concurrently with CSR build
    cudaEventRecord(evFork, 0);
    cudaStreamWaitEvent(s2, evFork, 0);
    k_gemm1<<<(NN + 255) / 256, 256, 0, s2>>>(x, W1);

    // main stream: CSR build
    cudaMemsetAsync(cnt_ptr, 0, NN * sizeof(int), 0);
    k_count<<<(NE / 4) / 256, 256>>>(dst);
    k_scan_local<<<SCAN_BLOCKS, 256>>>();
    cudaEventRecord(evScan, 0);
    k_scatter<<<(NE / 4) / 256, 256>>>(src, dst);   // uses local rowstart + blocksums

    // side stream: fixup (rowfinal+dinv) then fp16 scale — overlaps scatter
    cudaStreamWaitEvent(s2, evScan, 0);
    k_fixup<<<(NN + 255) / 256, 256, 0, s2>>>();
    k_scale<<<(NN * 2 + 255) / 256, 256, 0, s2>>>();
    cudaEventRecord(evSide, s2);

    // join, then aggregations
    cudaStreamWaitEvent(0, evSide, 0);
    k_gcn<<<(NN * 32 + 255) / 256, 256>>>(b1);
    k_sage<<<(NN * 32 + 255) / 256, 256>>>(Wl, Wr, b2, out);
}